// round 10
// baseline (speedup 1.0000x reference)
#include <cuda_runtime.h>
#include <cuda_bf16.h>
#include <cstdint>

typedef unsigned long long u64;

// Problem constants
#define TT 512
#define BB 32
#define EE 1024
#define HH 512
#define CC 24
#define NGATE 2048          // 4*HH
#define NPROJ 4096          // 2 dirs * 4H
#define MROWS (TT*BB)       // 16384

// -------------------- scratch (device globals; no allocation) --------------------
__device__ float g_xt[MROWS * EE];          // layer-0 input [t][b][e]
__device__ float g_inproj[MROWS * NPROJ];   // x@Wih^T + bias
__device__ float g_hout0[MROWS * 1024];     // layer-0 output [t][b][dir*512+j]
__device__ float g_hout1[MROWS * 1024];     // layer-1 output
__device__ float g_h[2 * 2 * BB * HH];      // [parity][dir][b*H + j]
__device__ unsigned g_bar_cnt[2];
__device__ unsigned g_bar_gen[2];
__device__ float g_crf_partial[BB];

// -------------------- PTX helpers --------------------
// packed f32x2 FMA (FFMA2 — real sm_103 HW, PTX-only pattern)
#define FMA2(acc, x, y) asm("fma.rn.f32x2 %0, %1, %2, %0;" : "+l"(acc) : "l"(x), "l"(y))
#define DUP2(d, s) asm("mov.b64 %0, {%1, %1};" : "=l"(d) : "f"(s))
__device__ __forceinline__ float sum2(u64 a) {
    float x, y;
    asm("mov.b64 {%0, %1}, %2;" : "=f"(x), "=f"(y) : "l"(a));
    return x + y;
}
__device__ __forceinline__ void unpack2(u64 a, float& x, float& y) {
    asm("mov.b64 {%0, %1}, %2;" : "=f"(x), "=f"(y) : "l"(a));
}

// -------------------- embedding gather --------------------
__global__ void gather_kernel(const int* __restrict__ x, const float* __restrict__ emb) {
    int idx = blockIdx.x * blockDim.x + threadIdx.x;   // over MROWS * 256
    int e4 = idx & 255;
    int tb = idx >> 8;
    int b = tb & 31, t = tb >> 5;
    int tok = x[b * TT + t];
    float4 v = ((const float4*)(emb + (size_t)tok * EE))[e4];
    ((float4*)(g_xt + (size_t)tb * EE))[e4] = v;
}

// -------------------- FFMA2 SGEMM --------------------
// C[m][n] = sum_k A[m][k]*W[n][k] + b1[n]+b2[n];  M=16384, N=4096, K=1024.
// Tile 128x128, 256 threads, thread = 8m x 8n (4 m-pairs packed in f32x2).
__global__ __launch_bounds__(256, 1)
void gemm_ffma2(const float* __restrict__ Wt,
                const float* __restrict__ b1, const float* __restrict__ b2,
                int a_sel) {
    __shared__ float As[2][16][128];
    __shared__ float Bs[2][16][128];
    __shared__ float sbias[128];

    const float* __restrict__ A = a_sel ? g_hout0 : g_xt;

    const int tid = threadIdx.x;
    const int tx = tid & 15;          // n group: n = tx*8 + j
    const int ty = tid >> 4;          // m group: m = ty*8 + i
    const int m0 = blockIdx.y * 128;
    const int n0 = blockIdx.x * 128;

    if (tid < 128) sbias[tid] = b1[n0 + tid] + b2[n0 + tid];

    // staging map: 4 threads per row, 16 floats (one k-panel) per row
    const int srow = tid >> 2;        // 0..63 (+64 for pass 1)
    const int skq  = (tid & 3) * 4;   // k offset within panel

    const float* a_base = A + (size_t)(m0 + srow) * 1024 + skq;
    const float* w_base = Wt + (size_t)(n0 + srow) * 1024 + skq;

    u64 acc[4][8];
#pragma unroll
    for (int ip = 0; ip < 4; ip++)
#pragma unroll
        for (int j = 0; j < 8; j++) acc[ip][j] = 0ull;

    float4 ra0, ra1, rw0, rw1;

    // prologue: panel 0
    ra0 = *(const float4*)(a_base);
    ra1 = *(const float4*)(a_base + (size_t)64 * 1024);
    rw0 = *(const float4*)(w_base);
    rw1 = *(const float4*)(w_base + (size_t)64 * 1024);
#pragma unroll
    for (int i = 0; i < 4; i++) {
        As[0][skq + i][srow]      = ((const float*)&ra0)[i];
        As[0][skq + i][srow + 64] = ((const float*)&ra1)[i];
        Bs[0][skq + i][srow]      = ((const float*)&rw0)[i];
        Bs[0][skq + i][srow + 64] = ((const float*)&rw1)[i];
    }
    __syncthreads();

    for (int p = 0; p < 64; p++) {
        const int buf = p & 1;
        if (p < 63) {
            size_t ko = (size_t)(p + 1) * 16;
            ra0 = *(const float4*)(a_base + ko);
            ra1 = *(const float4*)(a_base + (size_t)64 * 1024 + ko);
            rw0 = *(const float4*)(w_base + ko);
            rw1 = *(const float4*)(w_base + (size_t)64 * 1024 + ko);
        }

#pragma unroll
        for (int k = 0; k < 16; k++) {
            u64 a4[4];
#pragma unroll
            for (int ip = 0; ip < 4; ip++)
                a4[ip] = *(const u64*)&As[buf][k][ty * 8 + 2 * ip];
            float4 bv0 = *(const float4*)&Bs[buf][k][tx * 8];
            float4 bv1 = *(const float4*)&Bs[buf][k][tx * 8 + 4];
            u64 bd[8];
            DUP2(bd[0], bv0.x); DUP2(bd[1], bv0.y);
            DUP2(bd[2], bv0.z); DUP2(bd[3], bv0.w);
            DUP2(bd[4], bv1.x); DUP2(bd[5], bv1.y);
            DUP2(bd[6], bv1.z); DUP2(bd[7], bv1.w);
#pragma unroll
            for (int ip = 0; ip < 4; ip++)
#pragma unroll
                for (int j = 0; j < 8; j++)
                    FMA2(acc[ip][j], a4[ip], bd[j]);
        }

        if (p < 63) {
            const int nb = buf ^ 1;
#pragma unroll
            for (int i = 0; i < 4; i++) {
                As[nb][skq + i][srow]      = ((const float*)&ra0)[i];
                As[nb][skq + i][srow + 64] = ((const float*)&ra1)[i];
                Bs[nb][skq + i][srow]      = ((const float*)&rw0)[i];
                Bs[nb][skq + i][srow + 64] = ((const float*)&rw1)[i];
            }
        }
        __syncthreads();
    }

    // epilogue: unpack pairs, add bias, store
#pragma unroll
    for (int ip = 0; ip < 4; ip++) {
        int m = m0 + ty * 8 + 2 * ip;
        float lo[8], hi[8];
#pragma unroll
        for (int j = 0; j < 8; j++) {
            unpack2(acc[ip][j], lo[j], hi[j]);
            float bb = sbias[tx * 8 + j];
            lo[j] += bb; hi[j] += bb;
        }
        float* c0 = g_inproj + (size_t)m * NPROJ + n0 + tx * 8;
        float* c1 = c0 + NPROJ;
        *(float4*)(c0)     = make_float4(lo[0], lo[1], lo[2], lo[3]);
        *(float4*)(c0 + 4) = make_float4(lo[4], lo[5], lo[6], lo[7]);
        *(float4*)(c1)     = make_float4(hi[0], hi[1], hi[2], hi[3]);
        *(float4*)(c1 + 4) = make_float4(hi[4], hi[5], hi[6], hi[7]);
    }
}

// -------------------- zero h state + reset barriers --------------------
__global__ void zero_state_kernel() {
    int i = blockIdx.x * blockDim.x + threadIdx.x;
    if (i < 2 * 2 * BB * HH) g_h[i] = 0.f;
    if (i < 2) { g_bar_cnt[i] = 0u; g_bar_gen[i] = 0u; }
}

// -------------------- persistent bi-LSTM layer kernel (f32x2 FMA) --------------------
#define L_SMEM_FLOATS (32*512 + 32*516 + 32*33)
#define L_SMEM_BYTES  (L_SMEM_FLOATS * 4)

__global__ __launch_bounds__(256, 1)
void lstm_layer_persist(const float* __restrict__ whh_l, int layer) {
    extern __shared__ float smem[];
    float* ws  = smem;                          // [row=g*8+jl][512]
    float* hs  = smem + 32 * 512;               // [b][516]
    float* ips = smem + 32 * 512 + 32 * 516;    // [row][33]

    const int dir = (int)blockIdx.x >> 6;
    const int jt  = (int)blockIdx.x & 63;
    const int tid = threadIdx.x;
    const int w   = tid >> 5;
    const int b   = tid & 31;
    const int j   = jt * 8 + w;

    float* __restrict__ hout = layer ? g_hout1 : g_hout0;
    const float* __restrict__ wbase = whh_l + (size_t)dir * 4 * HH * HH;

    for (int i = tid; i < 32 * 128; i += 256) {
        int rw = i >> 7, k4 = i & 127;
        int gg = rw >> 3, jl = rw & 7;
        float4 v = *(const float4*)(wbase + (size_t)(gg * HH + jt * 8 + jl) * HH + k4 * 4);
        *(float4*)(ws + rw * 512 + k4 * 4) = v;
    }
    __syncthreads();

    const int sb  = tid >> 3;
    const int sg  = (tid >> 1) & 3;
    const int sj4 = tid & 1;
    const float* ipg_base = g_inproj + sb * NPROJ + dir * NGATE + sg * HH + jt * 8 + sj4 * 4;

    float c_reg = 0.f;

    for (int t = 0; t < TT; t++) {
        const int p  = t & 1;
        const int tt = dir ? (TT - 1 - t) : t;

        // prefetch step-invariant input projection BEFORE the grid barrier
        float4 ipv = *(const float4*)(ipg_base + (size_t)tt * 32 * NPROJ);

        if (t > 0) {
            __syncthreads();
            if (tid == 0) {
                __threadfence();
                unsigned a = atomicAdd(&g_bar_cnt[dir], 1u);
                if (a == 63u) {
                    g_bar_cnt[dir] = 0u;
                    __threadfence();
                    atomicExch(&g_bar_gen[dir], (unsigned)t);
                } else {
                    while (*(volatile unsigned*)&g_bar_gen[dir] < (unsigned)t) { }
                }
                __threadfence();
            }
            __syncthreads();
        }

        {
            const float* hsrc = g_h + (size_t)(p * 2 + dir) * (BB * HH);
            for (int i = tid; i < 32 * 128; i += 256) {
                int bb = i >> 7, k4 = i & 127;
                float4 v = *(const float4*)(hsrc + bb * 512 + k4 * 4);
                *(float4*)(hs + bb * 516 + k4 * 4) = v;
            }
        }
        {
            int rbase = sg * 8 + sj4 * 4;
            ips[(rbase + 0) * 33 + sb] = ipv.x;
            ips[(rbase + 1) * 33 + sb] = ipv.y;
            ips[(rbase + 2) * 33 + sb] = ipv.z;
            ips[(rbase + 3) * 33 + sb] = ipv.w;
        }
        __syncthreads();

        const ulonglong2* hp  = (const ulonglong2*)(hs + b * 516);
        const ulonglong2* w0p = (const ulonglong2*)(ws + (0 * 8 + w) * 512);
        const ulonglong2* w1p = (const ulonglong2*)(ws + (1 * 8 + w) * 512);
        const ulonglong2* w2p = (const ulonglong2*)(ws + (2 * 8 + w) * 512);
        const ulonglong2* w3p = (const ulonglong2*)(ws + (3 * 8 + w) * 512);

        u64 ac0 = 0, ac1 = 0, ac2 = 0, ac3 = 0, ac4 = 0, ac5 = 0, ac6 = 0, ac7 = 0;
#pragma unroll 8
        for (int k4 = 0; k4 < 128; k4++) {
            ulonglong2 h2 = hp[k4];
            ulonglong2 q0 = w0p[k4];
            ulonglong2 q1 = w1p[k4];
            ulonglong2 q2 = w2p[k4];
            ulonglong2 q3 = w3p[k4];
            FMA2(ac0, h2.x, q0.x);  FMA2(ac1, h2.y, q0.y);
            FMA2(ac2, h2.x, q1.x);  FMA2(ac3, h2.y, q1.y);
            FMA2(ac4, h2.x, q2.x);  FMA2(ac5, h2.y, q2.y);
            FMA2(ac6, h2.x, q3.x);  FMA2(ac7, h2.y, q3.y);
        }

        float gi = sum2(ac0) + sum2(ac1) + ips[(0 * 8 + w) * 33 + b];
        float gf = sum2(ac2) + sum2(ac3) + ips[(1 * 8 + w) * 33 + b];
        float gg = sum2(ac4) + sum2(ac5) + ips[(2 * 8 + w) * 33 + b];
        float go = sum2(ac6) + sum2(ac7) + ips[(3 * 8 + w) * 33 + b];

        gi = 1.f / (1.f + expf(-gi));
        gf = 1.f / (1.f + expf(-gf));
        gg = tanhf(gg);
        go = 1.f / (1.f + expf(-go));

        c_reg = gf * c_reg + gi * gg;
        float h = go * tanhf(c_reg);

        g_h[(size_t)((p ^ 1) * 2 + dir) * (BB * HH) + b * 512 + j] = h;
        hout[((size_t)tt * 32 + b) * 1024 + dir * HH + j] = h;
    }
}

// -------------------- FC: logits[b][t][c] --------------------
__global__ void fc_kernel(const float* __restrict__ fcw, const float* __restrict__ fcb,
                          float* __restrict__ out) {
    int row = blockIdx.x;          // t*BB + b
    int t = row >> 5;
    int b = row & 31;
    int c = threadIdx.x >> 5;      // 0..23
    int lane = threadIdx.x & 31;

    const float4* h4 = (const float4*)(g_hout1 + (size_t)row * 1024);
    const float4* w4 = (const float4*)(fcw + (size_t)c * 1024);
    float s = 0.f;
#pragma unroll 4
    for (int k = lane; k < 256; k += 32) {
        float4 a = h4[k], w = w4[k];
        s += a.x * w.x + a.y * w.y + a.z * w.z + a.w * w.w;
    }
#pragma unroll
    for (int o = 16; o; o >>= 1) s += __shfl_xor_sync(0xffffffffu, s, o);
    if (lane == 0) out[((size_t)b * TT + t) * CC + c] = s + fcb[c];
}

// -------------------- CRF per-batch block --------------------
__global__ void crf_block(const float* __restrict__ em, const int* __restrict__ labels,
                          const float* __restrict__ st, const float* __restrict__ en,
                          const float* __restrict__ tr) {
    const int b = blockIdx.x;
    const int cn = threadIdx.x;    // 32 threads, 24 active for DP
    __shared__ float trs[24][25];
    __shared__ float alpha[25];
    __shared__ int   labs[TT];
    __shared__ float s_en[24], s_st[24];

    for (int i = cn; i < 576; i += 32) trs[i / 24][i % 24] = tr[i];
    if (cn < 24) { s_en[cn] = en[cn]; s_st[cn] = st[cn]; }
    for (int i = cn; i < TT; i += 32) labs[i] = labels[b * TT + i];
    __syncwarp();

    const float* emb_ = em + (size_t)b * TT * CC;
    if (cn < 24) alpha[cn] = s_st[cn] + emb_[cn];
    __syncwarp();

    for (int t = 1; t < TT; t++) {
        float anew = 0.f;
        if (cn < 24) {
            float m = -1e30f;
#pragma unroll
            for (int cp = 0; cp < 24; cp++) m = fmaxf(m, alpha[cp] + trs[cp][cn]);
            float s = 0.f;
#pragma unroll
            for (int cp = 0; cp < 24; cp++) s += __expf(alpha[cp] + trs[cp][cn] - m);
            anew = m + __logf(s) + emb_[t * CC + cn];
        }
        __syncwarp();
        if (cn < 24) alpha[cn] = anew;
        __syncwarp();
    }

    // gold path score, warp-parallel over t
    float gs = 0.f;
    for (int t = cn; t < TT; t += 32) {
        int tg = labs[t];
        gs += emb_[t * CC + tg];
        if (t > 0) gs += trs[labs[t - 1]][tg];
    }
#pragma unroll
    for (int o = 16; o; o >>= 1) gs += __shfl_xor_sync(0xffffffffu, gs, o);

    if (cn == 0) {
        float m = -1e30f;
        for (int c = 0; c < 24; c++) m = fmaxf(m, alpha[c] + s_en[c]);
        float s = 0.f;
        for (int c = 0; c < 24; c++) s += __expf(alpha[c] + s_en[c] - m);
        float logZ = m + __logf(s);
        float num = gs + s_st[labs[0]] + s_en[labs[TT - 1]];
        g_crf_partial[b] = logZ - num;
    }
}

__global__ void crf_final(float* __restrict__ loss_out) {
    if (threadIdx.x == 0) {
        float L = 0.f;
        for (int b = 0; b < BB; b++) L += g_crf_partial[b];
        loss_out[0] = L;   // -llh
    }
}

// -------------------- launch --------------------
extern "C" void kernel_launch(void* const* d_in, const int* in_sizes, int n_in,
                              void* d_out, int out_size) {
    const int*   x         = (const int*)d_in[0];
    const int*   labels    = (const int*)d_in[1];
    const float* emb       = (const float*)d_in[2];
    const float* w_ih      = (const float*)d_in[3];
    const float* w_hh      = (const float*)d_in[4];
    const float* b_ih      = (const float*)d_in[5];
    const float* b_hh      = (const float*)d_in[6];
    const float* fc_w      = (const float*)d_in[7];
    const float* fc_b      = (const float*)d_in[8];
    const float* crf_start = (const float*)d_in[9];
    const float* crf_end   = (const float*)d_in[10];
    const float* crf_trans = (const float*)d_in[11];
    float* out = (float*)d_out;

    (void)in_sizes; (void)n_in; (void)out_size;

    cudaFuncSetAttribute(lstm_layer_persist,
                         cudaFuncAttributeMaxDynamicSharedMemorySize, L_SMEM_BYTES);

    // 1. embedding gather -> g_xt fp32
    gather_kernel<<<MROWS, 256>>>(x, emb);

    // 2. per-layer: FFMA2 input-projection GEMM, then persistent recurrence
    for (int l = 0; l < 2; l++) {
        const float* wih_l = w_ih + (size_t)l * 2 * NGATE * EE;
        const float* whh_l = w_hh + (size_t)l * 2 * NGATE * HH;
        const float* bih_l = b_ih + (size_t)l * NPROJ;
        const float* bhh_l = b_hh + (size_t)l * NPROJ;

        gemm_ffma2<<<dim3(NPROJ / 128, MROWS / 128), 256>>>(wih_l, bih_l, bhh_l, l);
        zero_state_kernel<<<256, 256>>>();
        lstm_layer_persist<<<128, 256, L_SMEM_BYTES>>>(whh_l, l);
    }

    // 3. FC -> logits into d_out as [b][t][c]
    fc_kernel<<<MROWS, 768>>>(fc_w, fc_b, out);

    // 4. CRF loss -> d_out[B*T*C]
    crf_block<<<BB, 32>>>(out, labels, crf_start, crf_end, crf_trans);
    crf_final<<<1, 32>>>(out + (size_t)BB * TT * CC);
}